// round 14
// baseline (speedup 1.0000x reference)
#include <cuda_runtime.h>
#include <cuda_fp16.h>
#include <cstdint>

// ---------------------------------------------------------------------------
// Problem dims
// ---------------------------------------------------------------------------
#define M_TOTAL 8192
#define K_IN    4096
#define N_OUT   11008

// GEMM tiling: 128x256 CTA tile, TWO independent 4-warp groups (128x128 each)
#define BM 128
#define BN 256                   // whole-CTA tile; each group owns 128 of N
#define BK 32                    // halfs per k-stage
#define STAGES 4
#define K_ITERS (K_IN / BK)      // 128
#define M_TILES (M_TOTAL / BM)   // 64
#define N_TILES (N_OUT / BN)     // 43
#define GROUP_M 16

#define LDS_B 80                 // smem bytes per 32-half row (64B + 16B pad)
#define A_STG (BM * LDS_B)       // 10240 (per-group private A copy)
#define B_STG (128 * LDS_B)      // 10240 (group's N-half of B)
#define STG   (A_STG + B_STG)    // 20480
#define GSIZE (STAGES * STG)     // 81920 per group
#define SMEM_TOTAL (2 * GSIZE)   // 163840

// ---------------------------------------------------------------------------
// Scratch (device globals: allocation-free kernel_launch)
// ---------------------------------------------------------------------------
__device__ __align__(256) __half g_A[(size_t)M_TOTAL * K_IN];   // fp16 activations
__device__ __align__(256) __half g_W[(size_t)N_OUT * K_IN];     // fp16 weights (exact)
__device__ float g_sumx[M_TOTAL];                                // per-row sum of fp16(x)

// ---------------------------------------------------------------------------
// PTX helpers (sm_80 baseline features only — compute_103 safe)
// ---------------------------------------------------------------------------
__device__ __forceinline__ uint32_t smem_u32(const void* p) {
    uint32_t a;
    asm("{ .reg .u64 t; cvta.to.shared.u64 t, %1; cvt.u32.u64 %0, t; }" : "=r"(a) : "l"(p));
    return a;
}
__device__ __forceinline__ void cp_async16(uint32_t dst, const void* src) {
    asm volatile("cp.async.cg.shared.global [%0], [%1], 16;" :: "r"(dst), "l"(src));
}
#define CP_COMMIT() asm volatile("cp.async.commit_group;")
#define CP_WAIT2()  asm volatile("cp.async.wait_group 2;")

// per-group named barrier: group g syncs its own 128 threads only
#define GBAR(g) asm volatile("bar.sync %0, 128;" :: "r"((g) + 1) : "memory")

__device__ __forceinline__ void ldsm_x4(uint32_t (&r)[4], uint32_t addr) {
    asm volatile("ldmatrix.sync.aligned.m8n8.x4.shared.b16 {%0,%1,%2,%3}, [%4];"
                 : "=r"(r[0]), "=r"(r[1]), "=r"(r[2]), "=r"(r[3]) : "r"(addr));
}
__device__ __forceinline__ void mma16816(float (&d)[4], const uint32_t (&a)[4],
                                         uint32_t b0, uint32_t b1) {
    asm volatile(
        "mma.sync.aligned.m16n8k16.row.col.f32.f16.f16.f32 "
        "{%0,%1,%2,%3}, {%4,%5,%6,%7}, {%8,%9}, {%0,%1,%2,%3};"
        : "+f"(d[0]), "+f"(d[1]), "+f"(d[2]), "+f"(d[3])
        : "r"(a[0]), "r"(a[1]), "r"(a[2]), "r"(a[3]), "r"(b0), "r"(b1));
}

// ---------------------------------------------------------------------------
// Fused prep kernel (single launch so ncu -s 5 lands on k_gemm)
// ---------------------------------------------------------------------------
__global__ void __launch_bounds__(256) k_prep(const float* __restrict__ in,
                                              const int* __restrict__ q) {
    int b = blockIdx.x;
    int t = threadIdx.x;
    if (b < M_TOTAL) {
        const float4* src = reinterpret_cast<const float4*>(in + (size_t)b * K_IN);
        uint2* dst = reinterpret_cast<uint2*>(g_A + (size_t)b * K_IN);
        float s = 0.f;
#pragma unroll
        for (int i = 0; i < 4; i++) {
            int e = i * 256 + t;
            float4 v = src[e];
            __half2 h0 = __floats2half2_rn(v.x, v.y);
            __half2 h1 = __floats2half2_rn(v.z, v.w);
            s += __low2float(h0) + __high2float(h0) + __low2float(h1) + __high2float(h1);
            uint2 p;
            p.x = *reinterpret_cast<uint32_t*>(&h0);
            p.y = *reinterpret_cast<uint32_t*>(&h1);
            dst[e] = p;
        }
#pragma unroll
        for (int off = 16; off; off >>= 1) s += __shfl_xor_sync(0xFFFFFFFFu, s, off);
        __shared__ float ws[8];
        if ((t & 31) == 0) ws[t >> 5] = s;
        __syncthreads();
        if (t == 0) {
            float tot = 0.f;
#pragma unroll
            for (int i = 0; i < 8; i++) tot += ws[i];
            g_sumx[b] = tot;
        }
    } else {
        int row = b - M_TOTAL;
        const int4* src = reinterpret_cast<const int4*>(q + (size_t)row * K_IN);
        uint2* dst = reinterpret_cast<uint2*>(g_W + (size_t)row * K_IN);
#pragma unroll
        for (int i = 0; i < 4; i++) {
            int e = i * 256 + t;
            int4 v = src[e];
            __half2 h0 = __floats2half2_rn((float)v.x, (float)v.y);
            __half2 h1 = __floats2half2_rn((float)v.z, (float)v.w);
            uint2 p;
            p.x = *reinterpret_cast<uint32_t*>(&h0);
            p.y = *reinterpret_cast<uint32_t*>(&h1);
            dst[e] = p;
        }
    }
}

// ---------------------------------------------------------------------------
// GEMM: per-group stage loader (128 threads: private A copy + B half)
// ---------------------------------------------------------------------------
__device__ __forceinline__ void load_stage(uint32_t s_base, const __half* Ag,
                                           const __half* Wg, int kt, int tg) {
    uint32_t sA = s_base, sB = s_base + A_STG;
    int c = tg & 3;           // 16B chunk within 64B row
    int r = tg >> 2;          // 0..31
    const __half* asrc = Ag + (size_t)r * K_IN + kt * BK + c * 8;
    const __half* bsrc = Wg + (size_t)r * K_IN + kt * BK + c * 8;
    uint32_t adst = sA + r * LDS_B + c * 16;
    uint32_t bdst = sB + r * LDS_B + c * 16;
#pragma unroll
    for (int i = 0; i < 4; i++) {
        cp_async16(adst + i * 32 * LDS_B, asrc + (size_t)i * 32 * K_IN);
        cp_async16(bdst + i * 32 * LDS_B, bsrc + (size_t)i * 32 * K_IN);
    }
}

__global__ void __launch_bounds__(256, 1) k_gemm(
    const __half* __restrict__ pA, const __half* __restrict__ pW,
    float* __restrict__ out,
    const float* __restrict__ w_scale, const int* __restrict__ w_zp,
    const float* __restrict__ bias, const float* __restrict__ sumx)
{
    extern __shared__ char smem[];
    uint32_t sm0 = smem_u32(smem);
    int t = threadIdx.x;
    int wid = t >> 5;
    int l = t & 31;
    int group = wid >> 2;                     // 0 or 1: independent pipeline
    int gw = wid & 3;                         // warp within group == SMSP id
    int tg = t & 127;                         // thread within group

    uint32_t gbase = sm0 + (uint32_t)group * GSIZE;

    // grouped rasterization: 16 M-tiles per supercolumn (L2 reuse of W)
    int bid = blockIdx.x;
    const int grp = GROUP_M * N_TILES;        // 688
    int g0 = bid / grp;
    int rem = bid - g0 * grp;
    int mtile = g0 * GROUP_M + (rem % GROUP_M);
    int ntile = rem / GROUP_M;

    int mbase = (gw & 1) * 64;                // 2 warps in M within group
    int nbase = (gw >> 1) * 64;               // 2 warps in N within group (of 128)
    int n_group_base = ntile * BN + group * 128;

    const __half* Ag = pA + (size_t)mtile * BM * K_IN;
    const __half* Wg = pW + (size_t)n_group_base * K_IN;

    float acc[4][8][4];
#pragma unroll
    for (int a = 0; a < 4; a++)
#pragma unroll
        for (int b = 0; b < 8; b++)
#pragma unroll
            for (int c = 0; c < 4; c++) acc[a][b][c] = 0.f;

    // prologue: fill 3 stages (per group), one commit group each
#pragma unroll
    for (int s = 0; s < STAGES - 1; s++) {
        load_stage(gbase + s * STG, Ag, Wg, s, tg);
        CP_COMMIT();
    }

    // lane-invariant ldmatrix address pieces (within group's 128x128 tile)
    uint32_t a_lane_off = (uint32_t)((l & 15) + mbase) * LDS_B + ((l >> 4) << 4);
    uint32_t b_lane_off = (uint32_t)((l & 7) + ((l >> 4) << 3) + nbase) * LDS_B
                        + (((l >> 3) & 1) << 4);

    // wait for stage 0, group-local barrier, prefetch k16=0 fragments
    CP_WAIT2();
    GBAR(group);

    uint32_t aCur[4][4], bCur[4][4];
    uint32_t aNxt[4][4], bNxt[4][4];
    {
        uint32_t sA = gbase, sB = gbase + A_STG;
#pragma unroll
        for (int mi = 0; mi < 4; mi++)
            ldsm_x4(aCur[mi], sA + a_lane_off + mi * 16 * LDS_B);
#pragma unroll
        for (int ni = 0; ni < 4; ni++)
            ldsm_x4(bCur[ni], sB + b_lane_off + ni * 16 * LDS_B);
    }

    int buf = 0;
    for (int kt = 0; kt < K_ITERS; kt++) {
        uint32_t sA = gbase + buf * STG;
        uint32_t sB = sA + A_STG;

        // ---- Phase A: interleave LDSM(nxt <- stage kt, k16=1) with MMA(cur) ----
#pragma unroll
        for (int p = 0; p < 16; p++) {
            if (p < 4)
                ldsm_x4(aNxt[p], sA + 32 + a_lane_off + p * 16 * LDS_B);
            else if (p < 8)
                ldsm_x4(bNxt[p - 4], sB + 32 + b_lane_off + (p - 4) * 16 * LDS_B);
            int mi = p >> 2, ni = p & 3;
            mma16816(acc[mi][2 * ni],     aCur[mi], bCur[ni][0], bCur[ni][1]);
            mma16816(acc[mi][2 * ni + 1], aCur[mi], bCur[ni][2], bCur[ni][3]);
        }

        // producer: stage kt+3 into buffer (kt-1)%4 (readers done pre-GBAR(kt-1))
        if (kt + STAGES - 1 < K_ITERS) {
            int nb = buf + (STAGES - 1); if (nb >= STAGES) nb -= STAGES;
            load_stage(gbase + nb * STG, Ag, Wg, kt + STAGES - 1, tg);
        }
        CP_COMMIT();

        // stage kt+1 resident; buffer kt%STAGES freed (group-local barrier only)
        CP_WAIT2();
        GBAR(group);

        // ---- Phase B: interleave LDSM(cur <- stage kt+1, k16=0) with MMA(nxt) ----
        int nbuf = buf + 1; if (nbuf == STAGES) nbuf = 0;
        uint32_t sA2 = gbase + nbuf * STG;
        uint32_t sB2 = sA2 + A_STG;
        bool more = (kt + 1 < K_ITERS);
#pragma unroll
        for (int p = 0; p < 16; p++) {
            if (more) {
                if (p < 4)
                    ldsm_x4(aCur[p], sA2 + a_lane_off + p * 16 * LDS_B);
                else if (p < 8)
                    ldsm_x4(bCur[p - 4], sB2 + b_lane_off + (p - 4) * 16 * LDS_B);
            }
            int mi = p >> 2, ni = p & 3;
            mma16816(acc[mi][2 * ni],     aNxt[mi], bNxt[ni][0], bNxt[ni][1]);
            mma16816(acc[mi][2 * ni + 1], aNxt[mi], bNxt[ni][2], bNxt[ni][3]);
        }

        buf = nbuf;
    }

    // ------------------ epilogue ------------------
    int g = l >> 2;
    int t2 = (l & 3) << 1;

    float scx[8][2], zpx[8][2], bix[8][2];
#pragma unroll
    for (int nj = 0; nj < 8; nj++) {
        int n = n_group_base + nbase + nj * 8 + t2;
        float2 sc = *reinterpret_cast<const float2*>(w_scale + n);
        int2   zp = *reinterpret_cast<const int2*>(w_zp + n);
        float2 bb = *reinterpret_cast<const float2*>(bias + n);
        scx[nj][0] = sc.x; scx[nj][1] = sc.y;
        zpx[nj][0] = (float)zp.x; zpx[nj][1] = (float)zp.y;
        bix[nj][0] = bb.x; bix[nj][1] = bb.y;
    }

#pragma unroll
    for (int mi = 0; mi < 4; mi++) {
        int m0 = mtile * BM + mbase + mi * 16 + g;
        float sx0 = sumx[m0];
        float sx1 = sumx[m0 + 8];
        float* o0 = out + (size_t)m0 * N_OUT + n_group_base + nbase + t2;
        float* o1 = o0 + (size_t)8 * N_OUT;
#pragma unroll
        for (int nj = 0; nj < 8; nj++) {
            float2 v0, v1;
            v0.x = (acc[mi][nj][0] - zpx[nj][0] * sx0) * scx[nj][0] + bix[nj][0];
            v0.y = (acc[mi][nj][1] - zpx[nj][1] * sx0) * scx[nj][1] + bix[nj][1];
            v1.x = (acc[mi][nj][2] - zpx[nj][0] * sx1) * scx[nj][0] + bix[nj][0];
            v1.y = (acc[mi][nj][3] - zpx[nj][1] * sx1) * scx[nj][1] + bix[nj][1];
            *reinterpret_cast<float2*>(o0 + nj * 8) = v0;
            *reinterpret_cast<float2*>(o1 + nj * 8) = v1;
        }
    }
}

// ---------------------------------------------------------------------------
// Host
// ---------------------------------------------------------------------------
extern "C" void kernel_launch(void* const* d_in, const int* in_sizes, int n_in,
                              void* d_out, int out_size) {
    const float* input   = (const float*)d_in[0];
    const int*   qweight = (const int*)d_in[1];
    const float* w_scale = (const float*)d_in[2];
    const int*   w_zp    = (const int*)d_in[3];
    const float* bias    = (const float*)d_in[4];
    float*       out     = (float*)d_out;

    void *pA = nullptr, *pW = nullptr, *pS = nullptr;
    cudaGetSymbolAddress(&pA, g_A);
    cudaGetSymbolAddress(&pW, g_W);
    cudaGetSymbolAddress(&pS, g_sumx);

    k_prep<<<M_TOTAL + N_OUT, 256>>>(input, qweight);

    cudaFuncSetAttribute(k_gemm, cudaFuncAttributeMaxDynamicSharedMemorySize, SMEM_TOTAL);
    k_gemm<<<M_TILES * N_TILES, 256, SMEM_TOTAL>>>(
        (const __half*)pA, (const __half*)pW, out, w_scale, w_zp, bias, (const float*)pS);
}

// round 15
// speedup vs baseline: 1.1134x; 1.1134x over previous
#include <cuda_runtime.h>
#include <cuda_fp16.h>
#include <cstdint>

// ---------------------------------------------------------------------------
// Problem dims
// ---------------------------------------------------------------------------
#define M_TOTAL 8192
#define K_IN    4096
#define N_OUT   11008

// GEMM tiling: 128x256x32 CTA, 8 warps @ 64x64 warp tiles, 1 CTA/SM
#define BM 128
#define BN 256
#define BK 32                    // halfs per k-stage
#define STAGES 5
#define K_ITERS (K_IN / BK)      // 128
#define M_TILES (M_TOTAL / BM)   // 64
#define N_TILES (N_OUT / BN)     // 43
#define GROUP_M 16

#define LDS_B 80                 // smem bytes per 32-half row (64B + 16B pad)
#define A_STG (BM * LDS_B)       // 10240
#define B_STG (BN * LDS_B)       // 20480
#define STG   (A_STG + B_STG)    // 30720
#define SMEM_TOTAL (STAGES * STG) // 153600

// ---------------------------------------------------------------------------
// Scratch (device globals: allocation-free kernel_launch)
// ---------------------------------------------------------------------------
__device__ __align__(256) __half g_A[(size_t)M_TOTAL * K_IN];   // fp16 activations
__device__ __align__(256) __half g_W[(size_t)N_OUT * K_IN];     // fp16 weights (exact)
__device__ float g_sumx[M_TOTAL];                                // per-row sum of fp16(x)

// ---------------------------------------------------------------------------
// PTX helpers (sm_80 baseline features only — compute_103 safe)
// ---------------------------------------------------------------------------
__device__ __forceinline__ uint32_t smem_u32(const void* p) {
    uint32_t a;
    asm("{ .reg .u64 t; cvta.to.shared.u64 t, %1; cvt.u32.u64 %0, t; }" : "=r"(a) : "l"(p));
    return a;
}
__device__ __forceinline__ void cp_async16(uint32_t dst, const void* src) {
    asm volatile("cp.async.cg.shared.global [%0], [%1], 16;" :: "r"(dst), "l"(src));
}
#define CP_COMMIT() asm volatile("cp.async.commit_group;")
#define CP_WAIT2()  asm volatile("cp.async.wait_group 2;")

__device__ __forceinline__ void ldsm_x4(uint32_t (&r)[4], uint32_t addr) {
    asm volatile("ldmatrix.sync.aligned.m8n8.x4.shared.b16 {%0,%1,%2,%3}, [%4];"
                 : "=r"(r[0]), "=r"(r[1]), "=r"(r[2]), "=r"(r[3]) : "r"(addr));
}
__device__ __forceinline__ void mma16816(float (&d)[4], const uint32_t (&a)[4],
                                         uint32_t b0, uint32_t b1) {
    asm volatile(
        "mma.sync.aligned.m16n8k16.row.col.f32.f16.f16.f32 "
        "{%0,%1,%2,%3}, {%4,%5,%6,%7}, {%8,%9}, {%0,%1,%2,%3};"
        : "+f"(d[0]), "+f"(d[1]), "+f"(d[2]), "+f"(d[3])
        : "r"(a[0]), "r"(a[1]), "r"(a[2]), "r"(a[3]), "r"(b0), "r"(b1));
}

// ---------------------------------------------------------------------------
// Fused prep kernel (single launch so ncu -s 5 lands on k_gemm)
// ---------------------------------------------------------------------------
__global__ void __launch_bounds__(256) k_prep(const float* __restrict__ in,
                                              const int* __restrict__ q) {
    int b = blockIdx.x;
    int t = threadIdx.x;
    if (b < M_TOTAL) {
        const float4* src = reinterpret_cast<const float4*>(in + (size_t)b * K_IN);
        uint2* dst = reinterpret_cast<uint2*>(g_A + (size_t)b * K_IN);
        float s = 0.f;
#pragma unroll
        for (int i = 0; i < 4; i++) {
            int e = i * 256 + t;
            float4 v = src[e];
            __half2 h0 = __floats2half2_rn(v.x, v.y);
            __half2 h1 = __floats2half2_rn(v.z, v.w);
            s += __low2float(h0) + __high2float(h0) + __low2float(h1) + __high2float(h1);
            uint2 p;
            p.x = *reinterpret_cast<uint32_t*>(&h0);
            p.y = *reinterpret_cast<uint32_t*>(&h1);
            dst[e] = p;
        }
#pragma unroll
        for (int off = 16; off; off >>= 1) s += __shfl_xor_sync(0xFFFFFFFFu, s, off);
        __shared__ float ws[8];
        if ((t & 31) == 0) ws[t >> 5] = s;
        __syncthreads();
        if (t == 0) {
            float tot = 0.f;
#pragma unroll
            for (int i = 0; i < 8; i++) tot += ws[i];
            g_sumx[b] = tot;
        }
    } else {
        int row = b - M_TOTAL;
        const int4* src = reinterpret_cast<const int4*>(q + (size_t)row * K_IN);
        uint2* dst = reinterpret_cast<uint2*>(g_W + (size_t)row * K_IN);
#pragma unroll
        for (int i = 0; i < 4; i++) {
            int e = i * 256 + t;
            int4 v = src[e];
            __half2 h0 = __floats2half2_rn((float)v.x, (float)v.y);
            __half2 h1 = __floats2half2_rn((float)v.z, (float)v.w);
            uint2 p;
            p.x = *reinterpret_cast<uint32_t*>(&h0);
            p.y = *reinterpret_cast<uint32_t*>(&h1);
            dst[e] = p;
        }
    }
}

// ---------------------------------------------------------------------------
// GEMM
// ---------------------------------------------------------------------------
__device__ __forceinline__ void load_stage(uint32_t s_base, const __half* Ag,
                                           const __half* Wg, int kt, int t) {
    uint32_t sA = s_base, sB = s_base + A_STG;
    int c = t & 3;            // 16B chunk within 64B row
    int r = t >> 2;           // 0..63
    const __half* asrc = Ag + (size_t)r * K_IN + kt * BK + c * 8;
    uint32_t adst = sA + r * LDS_B + c * 16;
    cp_async16(adst, asrc);
    cp_async16(adst + 64 * LDS_B, asrc + (size_t)64 * K_IN);
    const __half* bsrc = Wg + (size_t)r * K_IN + kt * BK + c * 8;
    uint32_t bdst = sB + r * LDS_B + c * 16;
#pragma unroll
    for (int i = 0; i < 4; i++)
        cp_async16(bdst + i * 64 * LDS_B, bsrc + (size_t)i * 64 * K_IN);
}

__global__ void __launch_bounds__(256, 1) k_gemm(
    const __half* __restrict__ pA, const __half* __restrict__ pW,
    float* __restrict__ out,
    const float* __restrict__ w_scale, const int* __restrict__ w_zp,
    const float* __restrict__ bias, const float* __restrict__ sumx)
{
    extern __shared__ char smem[];
    uint32_t sm0 = smem_u32(smem);
    int t = threadIdx.x;
    int wid = t >> 5;
    int l = t & 31;

    // grouped rasterization: 16 M-tiles per supercolumn (L2 reuse of W)
    int bid = blockIdx.x;
    const int group = GROUP_M * N_TILES;      // 688
    int g0 = bid / group;
    int rem = bid - g0 * group;
    int mtile = g0 * GROUP_M + (rem % GROUP_M);
    int ntile = rem / GROUP_M;

    int mbase = (wid & 1) * 64;               // 2 warps in M
    int nbase = (wid >> 1) * 64;              // 4 warps in N

    const __half* Ag = pA + (size_t)mtile * BM * K_IN;
    const __half* Wg = pW + (size_t)ntile * BN * K_IN;

    float acc[4][8][4];
#pragma unroll
    for (int a = 0; a < 4; a++)
#pragma unroll
        for (int b = 0; b < 8; b++)
#pragma unroll
            for (int c = 0; c < 4; c++) acc[a][b][c] = 0.f;

    // prologue: fill 4 stages, one commit group each
#pragma unroll
    for (int s = 0; s < STAGES - 1; s++) {
        load_stage(sm0 + s * STG, Ag, Wg, s, t);
        CP_COMMIT();
    }

    // lane-invariant ldmatrix address pieces
    uint32_t a_lane_off = (uint32_t)((l & 15) + mbase) * LDS_B + ((l >> 4) << 4);
    uint32_t b_lane_off = (uint32_t)((l & 7) + ((l >> 4) << 3) + nbase) * LDS_B
                        + (((l >> 3) & 1) << 4);

    // wait for stages 0,1 and prefetch k16=0 fragments of stage 0
    CP_WAIT2();
    __syncthreads();

    uint32_t aCur[4][4], bCur[4][4];   // fragments feeding the current MMA set
    uint32_t aNxt[4][4], bNxt[4][4];   // fragments being loaded
    {
        uint32_t sA = sm0, sB = sm0 + A_STG;
#pragma unroll
        for (int mi = 0; mi < 4; mi++)
            ldsm_x4(aCur[mi], sA + a_lane_off + mi * 16 * LDS_B);
#pragma unroll
        for (int ni = 0; ni < 4; ni++)
            ldsm_x4(bCur[ni], sB + b_lane_off + ni * 16 * LDS_B);
    }

    int buf = 0;
    for (int kt = 0; kt < K_ITERS; kt++) {
        uint32_t sA = sm0 + buf * STG;
        uint32_t sB = sA + A_STG;

        // ---- Phase A: interleave LDSM(nxt <- stage kt, k16=1) with MMA(cur) ----
#pragma unroll
        for (int p = 0; p < 16; p++) {
            if (p < 4)
                ldsm_x4(aNxt[p], sA + 32 + a_lane_off + p * 16 * LDS_B);
            else if (p < 8)
                ldsm_x4(bNxt[p - 4], sB + 32 + b_lane_off + (p - 4) * 16 * LDS_B);
            int mi = p >> 2, ni = p & 3;
            mma16816(acc[mi][2 * ni],     aCur[mi], bCur[ni][0], bCur[ni][1]);
            mma16816(acc[mi][2 * ni + 1], aCur[mi], bCur[ni][2], bCur[ni][3]);
        }

        // Wait for stage kt+1 (committed one full iteration ago -> rarely stalls)
        // and free buffer kt%STAGES for this iteration's trailing producer.
        CP_WAIT2();
        __syncthreads();

        // ---- Phase B: interleave LDSM(cur <- stage kt+1, k16=0) with MMA(nxt) ----
        int nbuf = buf + 1; if (nbuf == STAGES) nbuf = 0;
        uint32_t sA2 = sm0 + nbuf * STG;
        uint32_t sB2 = sA2 + A_STG;
        bool more = (kt + 1 < K_ITERS);
#pragma unroll
        for (int p = 0; p < 16; p++) {
            if (more) {
                if (p < 4)
                    ldsm_x4(aCur[p], sA2 + a_lane_off + p * 16 * LDS_B);
                else if (p < 8)
                    ldsm_x4(bCur[p - 4], sB2 + b_lane_off + (p - 4) * 16 * LDS_B);
            }
            int mi = p >> 2, ni = p & 3;
            mma16816(acc[mi][2 * ni],     aNxt[mi], bNxt[ni][0], bNxt[ni][1]);
            mma16816(acc[mi][2 * ni + 1], aNxt[mi], bNxt[ni][2], bNxt[ni][3]);
        }

        // ---- trailing producer: stage kt+4 into buffer (kt-1)%5 ----
        // Safe: stage kt-1's last reads (Phase A of kt-1 / prefetch of kt-2)
        // all precede the barrier above. Committing here gives the NEXT
        // iteration's wait a full Phase-A of slack.
        if (kt + STAGES - 1 < K_ITERS) {
            int nb = buf + (STAGES - 1); if (nb >= STAGES) nb -= STAGES;
            load_stage(sm0 + nb * STG, Ag, Wg, kt + STAGES - 1, t);
        }
        CP_COMMIT();

        buf = nbuf;
    }

    // ------------------ epilogue ------------------
    int g = l >> 2;
    int t2 = (l & 3) << 1;

    float scx[8][2], zpx[8][2], bix[8][2];
#pragma unroll
    for (int nj = 0; nj < 8; nj++) {
        int n = ntile * BN + nbase + nj * 8 + t2;
        float2 sc = *reinterpret_cast<const float2*>(w_scale + n);
        int2   zp = *reinterpret_cast<const int2*>(w_zp + n);
        float2 bb = *reinterpret_cast<const float2*>(bias + n);
        scx[nj][0] = sc.x; scx[nj][1] = sc.y;
        zpx[nj][0] = (float)zp.x; zpx[nj][1] = (float)zp.y;
        bix[nj][0] = bb.x; bix[nj][1] = bb.y;
    }

#pragma unroll
    for (int mi = 0; mi < 4; mi++) {
        int m0 = mtile * BM + mbase + mi * 16 + g;
        float sx0 = sumx[m0];
        float sx1 = sumx[m0 + 8];
        float* o0 = out + (size_t)m0 * N_OUT + ntile * BN + nbase + t2;
        float* o1 = o0 + (size_t)8 * N_OUT;
#pragma unroll
        for (int nj = 0; nj < 8; nj++) {
            float2 v0, v1;
            v0.x = (acc[mi][nj][0] - zpx[nj][0] * sx0) * scx[nj][0] + bix[nj][0];
            v0.y = (acc[mi][nj][1] - zpx[nj][1] * sx0) * scx[nj][1] + bix[nj][1];
            v1.x = (acc[mi][nj][2] - zpx[nj][0] * sx1) * scx[nj][0] + bix[nj][0];
            v1.y = (acc[mi][nj][3] - zpx[nj][1] * sx1) * scx[nj][1] + bix[nj][1];
            *reinterpret_cast<float2*>(o0 + nj * 8) = v0;
            *reinterpret_cast<float2*>(o1 + nj * 8) = v1;
        }
    }
}

// ---------------------------------------------------------------------------
// Host
// ---------------------------------------------------------------------------
extern "C" void kernel_launch(void* const* d_in, const int* in_sizes, int n_in,
                              void* d_out, int out_size) {
    const float* input   = (const float*)d_in[0];
    const int*   qweight = (const int*)d_in[1];
    const float* w_scale = (const float*)d_in[2];
    const int*   w_zp    = (const int*)d_in[3];
    const float* bias    = (const float*)d_in[4];
    float*       out     = (float*)d_out;

    void *pA = nullptr, *pW = nullptr, *pS = nullptr;
    cudaGetSymbolAddress(&pA, g_A);
    cudaGetSymbolAddress(&pW, g_W);
    cudaGetSymbolAddress(&pS, g_sumx);

    k_prep<<<M_TOTAL + N_OUT, 256>>>(input, qweight);

    cudaFuncSetAttribute(k_gemm, cudaFuncAttributeMaxDynamicSharedMemorySize, SMEM_TOTAL);
    k_gemm<<<M_TILES * N_TILES, 256, SMEM_TOTAL>>>(
        (const __half*)pA, (const __half*)pW, out, w_scale, w_zp, bias, (const float*)pS);
}